// round 9
// baseline (speedup 1.0000x reference)
#include <cuda_runtime.h>
#include <cuda_bf16.h>
#include <stdint.h>
#include <math.h>

#define NR 8192
#define KD 512
#define TM 128
#define KC 64                      // int8 k-chunk: 64 B/row
#define NCH (KD / KC)              // 8 K-chunks
#define NB (NR / TM)               // 64 row blocks
#define NTILES (NB * (NB + 1) / 2) // 2080 upper-triangle tiles
#define ROWB 80                    // padded smem row stride (64B data + 16B pad)
#define TAU_INV 0.01f
#define QSCALE 20.0f
#define QINV2 (1.0f / (QSCALE * QSCALE))   // 0.0025

__device__ double g_acc;
__device__ float g_sq[NR];
__device__ int8_t g_zb[(size_t)NR * KD];   // int8, 4 MB

// ---------------- helpers ----------------
__device__ __forceinline__ uint32_t smem_u32(const void* p) {
    uint32_t a;
    asm("{ .reg .u64 t; cvta.to.shared.u64 t, %1; cvt.u32.u64 %0, t; }"
        : "=r"(a) : "l"(p));
    return a;
}
__device__ __forceinline__ void cp_async16(uint32_t s, const void* g) {
    asm volatile("cp.async.cg.shared.global [%0], [%1], 16;" :: "r"(s), "l"(g));
}
#define CP_COMMIT() asm volatile("cp.async.commit_group;" ::: "memory")
#define CP_WAIT1()  asm volatile("cp.async.wait_group 1;" ::: "memory")

__device__ __forceinline__ void ldm_x4(uint32_t* r, uint32_t a) {
    asm volatile("ldmatrix.sync.aligned.m8n8.x4.shared.b16 {%0,%1,%2,%3}, [%4];"
        : "=r"(r[0]), "=r"(r[1]), "=r"(r[2]), "=r"(r[3]) : "r"(a));
}
__device__ __forceinline__ void mma_s8(int32_t* d, const uint32_t* a, const uint32_t* b) {
    asm volatile(
        "mma.sync.aligned.m16n8k32.row.col.s32.s8.s8.s32 "
        "{%0,%1,%2,%3}, {%4,%5,%6,%7}, {%8,%9}, {%0,%1,%2,%3};"
        : "+r"(d[0]), "+r"(d[1]), "+r"(d[2]), "+r"(d[3])
        : "r"(a[0]), "r"(a[1]), "r"(a[2]), "r"(a[3]), "r"(b[0]), "r"(b[1]));
}
__device__ __forceinline__ uint32_t q4(float x, float y, float z, float w) {
    // round-to-nearest, clamp to [-127,127], pack 4 bytes
    int a = __float2int_rn(fminf(fmaxf(x * QSCALE, -127.0f), 127.0f));
    int b = __float2int_rn(fminf(fmaxf(y * QSCALE, -127.0f), 127.0f));
    int c = __float2int_rn(fminf(fmaxf(z * QSCALE, -127.0f), 127.0f));
    int d = __float2int_rn(fminf(fmaxf(w * QSCALE, -127.0f), 127.0f));
    return (uint32_t)(a & 0xFF) | ((uint32_t)(b & 0xFF) << 8) |
           ((uint32_t)(c & 0xFF) << 16) | ((uint32_t)(d & 0xFF) << 24);
}

// ---------------- Kernel 1: quantize to int8 + fp32 row norms (1 warp/row) ----------------
__global__ void __launch_bounds__(256) prep_kernel(const float* __restrict__ z) {
    const int w = threadIdx.x >> 5, lane = threadIdx.x & 31;
    const int row = blockIdx.x * 8 + w;
    const float4* zr = (const float4*)(z + (size_t)row * KD);
    uint32_t* dst = (uint32_t*)(g_zb + (size_t)row * KD);
    float s = 0.0f;
    #pragma unroll
    for (int i = 0; i < 4; i++) {
        const float4 v = zr[lane + 32 * i];
        s += v.x * v.x + v.y * v.y + v.z * v.z + v.w * v.w;
        dst[lane + 32 * i] = q4(v.x, v.y, v.z, v.w);
    }
    #pragma unroll
    for (int o = 16; o > 0; o >>= 1) s += __shfl_down_sync(0xffffffffu, s, o);
    if (lane == 0) {
        g_sq[row] = s;
        if (row == 0) g_acc = 0.0;
    }
}

// ---------------- Kernel 2: INT8 IMMA GEMM + fused exp-reduce ----------------
__global__ void __launch_bounds__(256) pair_mma_kernel() {
    __shared__ __align__(16) char sm[2][2][TM * ROWB];   // [stage][A/B]  40 KB
    __shared__ float s_sqi[TM], s_sqj[TM];
    __shared__ float s_red[8];

    const int tid = threadIdx.x;
    const int wid = tid >> 5;
    const int lid = tid & 31;
    const int wr = wid >> 1;          // warp row 0..3  (32 rows each)
    const int wc = wid & 1;           // warp col 0..1  (64 cols each)

    // linear tile index -> (bi, bj) upper triangle
    int t = blockIdx.x, bi = 0;
    while (t >= NB - bi) { t -= NB - bi; bi++; }
    const int bj = bi + t;

    const int8_t* Ag = g_zb + (size_t)(bi * TM) * KD;
    const int8_t* Bg = g_zb + (size_t)(bj * TM) * KD;

    uint32_t smA[2], smB[2];
    #pragma unroll
    for (int s = 0; s < 2; s++) {
        smA[s] = smem_u32(sm[s][0]);
        smB[s] = smem_u32(sm[s][1]);
    }

    // chunk = 128 rows x 64 B = 512 x 16B units; 2 slots/thread/matrix
    auto load_chunk = [&](int kc, int st) {
        #pragma unroll
        for (int i = 0; i < 2; i++) {
            const int f = tid + (i << 8);
            const int r = f >> 2, u = f & 3;
            const uint32_t so = (uint32_t)r * ROWB + (uint32_t)u * 16;
            const size_t go = (size_t)r * KD + (size_t)kc * KC + (size_t)u * 16;
            cp_async16(smA[st] + so, Ag + go);
            cp_async16(smB[st] + so, Bg + go);
        }
    };

    int32_t d[2][8][4];
    #pragma unroll
    for (int mi = 0; mi < 2; mi++)
        #pragma unroll
        for (int ni = 0; ni < 8; ni++)
            #pragma unroll
            for (int q = 0; q < 4; q++) d[mi][ni][q] = 0;

    load_chunk(0, 0); CP_COMMIT();
    load_chunk(1, 1); CP_COMMIT();

    // fragment address geometry (byte-identical to fp8 m16n8k32 case)
    const int a_row = (lid & 15);
    const int a_jofs = (lid >> 4);                     // 16B k-half
    const int b_row = (lid & 7) + ((lid >> 4) << 3);
    const int b_jofs = ((lid >> 3) & 1);

    for (int kc = 0; kc < NCH; kc++) {
        CP_WAIT1();
        __syncthreads();
        const int st = kc & 1;
        #pragma unroll
        for (int kk = 0; kk < 2; kk++) {               // two k=32 steps per chunk
            uint32_t afr[2][4];
            #pragma unroll
            for (int mi = 0; mi < 2; mi++) {
                const int r = wr * 32 + mi * 16 + a_row;
                ldm_x4(afr[mi], smA[st] + (uint32_t)r * ROWB +
                                 (uint32_t)(kk * 32 + a_jofs * 16));
            }
            uint32_t bfr[16];
            #pragma unroll
            for (int nb = 0; nb < 4; nb++) {
                const int n = wc * 64 + nb * 16 + b_row;
                ldm_x4(bfr + nb * 4, smB[st] + (uint32_t)n * ROWB +
                                      (uint32_t)(kk * 32 + b_jofs * 16));
            }
            #pragma unroll
            for (int mi = 0; mi < 2; mi++)
                #pragma unroll
                for (int ni = 0; ni < 8; ni++)
                    mma_s8(d[mi][ni], afr[mi], bfr + ni * 2);
        }
        __syncthreads();
        if (kc + 2 < NCH) load_chunk(kc + 2, st);
        CP_COMMIT();
    }

    if (tid < TM) {
        s_sqi[tid] = g_sq[bi * TM + tid];
        s_sqj[tid] = g_sq[bj * TM + tid];
    }
    __syncthreads();

    // epilogue: dot = acc/QSCALE^2; D = sqi + sqj - 2*dot -> exp -> sum (skip diag)
    const int g = lid >> 2, tt = lid & 3;
    const bool diag = (bi == bj);
    const float c2 = 2.0f * QINV2;
    float lsum = 0.0f;
    #pragma unroll
    for (int mi = 0; mi < 2; mi++) {
        const int rl0 = wr * 32 + mi * 16 + g;
        const int rl1 = rl0 + 8;
        const float si0 = s_sqi[rl0], si1 = s_sqi[rl1];
        #pragma unroll
        for (int ni = 0; ni < 8; ni++) {
            const int c0 = wc * 64 + ni * 8 + 2 * tt;
            const int c1 = c0 + 1;
            const float sj0 = s_sqj[c0], sj1 = s_sqj[c1];
            float e00 = __expf(-(si0 + sj0 - c2 * (float)d[mi][ni][0]) * TAU_INV);
            float e01 = __expf(-(si0 + sj1 - c2 * (float)d[mi][ni][1]) * TAU_INV);
            float e10 = __expf(-(si1 + sj0 - c2 * (float)d[mi][ni][2]) * TAU_INV);
            float e11 = __expf(-(si1 + sj1 - c2 * (float)d[mi][ni][3]) * TAU_INV);
            if (diag) {
                if (rl0 == c0) e00 = 0.0f;
                if (rl0 == c1) e01 = 0.0f;
                if (rl1 == c0) e10 = 0.0f;
                if (rl1 == c1) e11 = 0.0f;
            }
            lsum += (e00 + e01) + (e10 + e11);
        }
    }

    #pragma unroll
    for (int o = 16; o > 0; o >>= 1) lsum += __shfl_down_sync(0xffffffffu, lsum, o);
    if (lid == 0) s_red[wid] = lsum;
    __syncthreads();
    if (tid == 0) {
        float bsum = 0.0f;
        #pragma unroll
        for (int i = 0; i < 8; i++) bsum += s_red[i];
        atomicAdd(&g_acc, diag ? (double)bsum : 2.0 * (double)bsum);
    }
}

// ---------------- Kernel 3: finalize ----------------
__global__ void fin_kernel(float* __restrict__ out) {
    out[0] = (float)log(g_acc / ((double)NR * (double)(NR - 1)));
}

extern "C" void kernel_launch(void* const* d_in, const int* in_sizes, int n_in,
                              void* d_out, int out_size) {
    const float* z = (const float*)d_in[0];
    float* out = (float*)d_out;

    prep_kernel<<<NR / 8, 256>>>(z);
    pair_mma_kernel<<<NTILES, 256>>>();
    fin_kernel<<<1, 1>>>(out);
}

// round 10
// speedup vs baseline: 2.0647x; 2.0647x over previous
#include <cuda_runtime.h>
#include <cuda_fp16.h>
#include <stdint.h>
#include <math.h>

#define NR 8192
#define KD 512
#define TM 128
#define KC 32                      // f16 k-chunk: 64 B/row
#define NCH (KD / KC)              // 16 K-chunks
#define NB (NR / TM)               // 64 row blocks
#define NTILES (NB * (NB + 1) / 2) // 2080 upper-triangle tiles
#define ROWB 80                    // padded smem row stride (64B data + 16B pad)
#define TAU_INV 0.01f

__device__ double g_acc;
__device__ float g_sq[NR];
__device__ __half g_zb[(size_t)NR * KD];   // f16, 8 MB

// ---------------- helpers ----------------
__device__ __forceinline__ uint32_t smem_u32(const void* p) {
    uint32_t a;
    asm("{ .reg .u64 t; cvta.to.shared.u64 t, %1; cvt.u32.u64 %0, t; }"
        : "=r"(a) : "l"(p));
    return a;
}
__device__ __forceinline__ void cp_async16(uint32_t s, const void* g) {
    asm volatile("cp.async.cg.shared.global [%0], [%1], 16;" :: "r"(s), "l"(g));
}
#define CP_COMMIT() asm volatile("cp.async.commit_group;" ::: "memory")
#define CP_WAIT1()  asm volatile("cp.async.wait_group 1;" ::: "memory")

__device__ __forceinline__ void ldm_x4(uint32_t* r, uint32_t a) {
    asm volatile("ldmatrix.sync.aligned.m8n8.x4.shared.b16 {%0,%1,%2,%3}, [%4];"
        : "=r"(r[0]), "=r"(r[1]), "=r"(r[2]), "=r"(r[3]) : "r"(a));
}
// f16 x f16 -> f16 accumulate (2 regs = 4 halves: {c0,c1},{c2,c3})
__device__ __forceinline__ void mma_f16acc(uint32_t* d, const uint32_t* a, const uint32_t* b) {
    asm volatile(
        "mma.sync.aligned.m16n8k16.row.col.f16.f16.f16.f16 "
        "{%0,%1}, {%2,%3,%4,%5}, {%6,%7}, {%0,%1};"
        : "+r"(d[0]), "+r"(d[1])
        : "r"(a[0]), "r"(a[1]), "r"(a[2]), "r"(a[3]), "r"(b[0]), "r"(b[1]));
}

// ---------------- Kernel 1: convert to f16 + fp32 row norms (1 warp/row) ----------------
__global__ void __launch_bounds__(256) prep_kernel(const float* __restrict__ z) {
    const int w = threadIdx.x >> 5, lane = threadIdx.x & 31;
    const int row = blockIdx.x * 8 + w;
    const float4* zr = (const float4*)(z + (size_t)row * KD);
    __half2* dst = (__half2*)(g_zb + (size_t)row * KD);
    float s = 0.0f;
    #pragma unroll
    for (int i = 0; i < 4; i++) {
        const float4 v = zr[lane + 32 * i];
        s += v.x * v.x + v.y * v.y + v.z * v.z + v.w * v.w;
        dst[2 * (lane + 32 * i)]     = __floats2half2_rn(v.x, v.y);
        dst[2 * (lane + 32 * i) + 1] = __floats2half2_rn(v.z, v.w);
    }
    #pragma unroll
    for (int o = 16; o > 0; o >>= 1) s += __shfl_down_sync(0xffffffffu, s, o);
    if (lane == 0) {
        g_sq[row] = s;
        if (row == 0) g_acc = 0.0;
    }
}

// ---------------- Kernel 2: f16-accum HMMA GEMM + fused exp-reduce ----------------
__global__ void __launch_bounds__(256) pair_mma_kernel() {
    __shared__ __align__(16) char sm[2][2][TM * ROWB];   // [stage][A/B]  40 KB
    __shared__ float s_sqi[TM], s_sqj[TM];
    __shared__ float s_red[8];

    const int tid = threadIdx.x;
    const int wid = tid >> 5;
    const int lid = tid & 31;
    const int wr = wid >> 1;          // warp row 0..3  (32 rows each)
    const int wc = wid & 1;           // warp col 0..1  (64 cols each)

    // linear tile index -> (bi, bj) upper triangle
    int t = blockIdx.x, bi = 0;
    while (t >= NB - bi) { t -= NB - bi; bi++; }
    const int bj = bi + t;

    const __half* Ag = g_zb + (size_t)(bi * TM) * KD;
    const __half* Bg = g_zb + (size_t)(bj * TM) * KD;

    uint32_t smA[2], smB[2];
    #pragma unroll
    for (int s = 0; s < 2; s++) {
        smA[s] = smem_u32(sm[s][0]);
        smB[s] = smem_u32(sm[s][1]);
    }

    // chunk = 128 rows x 64 B = 512 x 16B units; 2 slots/thread/matrix
    auto load_chunk = [&](int kc, int st) {
        #pragma unroll
        for (int i = 0; i < 2; i++) {
            const int f = tid + (i << 8);
            const int r = f >> 2, u = f & 3;
            const uint32_t so = (uint32_t)r * ROWB + (uint32_t)u * 16;
            const size_t go = (size_t)r * KD + (size_t)kc * KC + (size_t)u * 8;
            cp_async16(smA[st] + so, Ag + go);
            cp_async16(smB[st] + so, Bg + go);
        }
    };

    uint32_t d[2][8][2];
    #pragma unroll
    for (int mi = 0; mi < 2; mi++)
        #pragma unroll
        for (int ni = 0; ni < 8; ni++) {
            d[mi][ni][0] = 0u;
            d[mi][ni][1] = 0u;
        }

    load_chunk(0, 0); CP_COMMIT();
    load_chunk(1, 1); CP_COMMIT();

    // fragment address geometry (identical to round-3 bf16 m16n8k16)
    const int a_row = (lid & 15);
    const int a_jofs = (lid >> 4);
    const int b_row = (lid & 7) + ((lid >> 4) << 3);
    const int b_jofs = ((lid >> 3) & 1);

    for (int kc = 0; kc < NCH; kc++) {
        CP_WAIT1();
        __syncthreads();
        const int st = kc & 1;
        #pragma unroll
        for (int kk = 0; kk < 2; kk++) {               // two k=16 steps per chunk
            uint32_t afr[2][4];
            #pragma unroll
            for (int mi = 0; mi < 2; mi++) {
                const int r = wr * 32 + mi * 16 + a_row;
                ldm_x4(afr[mi], smA[st] + (uint32_t)r * ROWB +
                                 (uint32_t)(kk * 2 + a_jofs) * 16);
            }
            uint32_t bfr[16];
            #pragma unroll
            for (int nb = 0; nb < 4; nb++) {
                const int n = wc * 64 + nb * 16 + b_row;
                ldm_x4(bfr + nb * 4, smB[st] + (uint32_t)n * ROWB +
                                      (uint32_t)(kk * 2 + b_jofs) * 16);
            }
            #pragma unroll
            for (int mi = 0; mi < 2; mi++)
                #pragma unroll
                for (int ni = 0; ni < 8; ni++)
                    mma_f16acc(d[mi][ni], afr[mi], bfr + ni * 2);
        }
        __syncthreads();
        if (kc + 2 < NCH) load_chunk(kc + 2, st);
        CP_COMMIT();
    }

    if (tid < TM) {
        s_sqi[tid] = g_sq[bi * TM + tid];
        s_sqj[tid] = g_sq[bj * TM + tid];
    }
    __syncthreads();

    // epilogue: D = sqi + sqj - 2*dot -> exp -> sum (skip diagonal)
    const int g = lid >> 2, tt = lid & 3;
    const bool diag = (bi == bj);
    float lsum = 0.0f;
    #pragma unroll
    for (int mi = 0; mi < 2; mi++) {
        const int rl0 = wr * 32 + mi * 16 + g;
        const int rl1 = rl0 + 8;
        const float si0 = s_sqi[rl0], si1 = s_sqi[rl1];
        #pragma unroll
        for (int ni = 0; ni < 8; ni++) {
            const int c0 = wc * 64 + ni * 8 + 2 * tt;
            const int c1 = c0 + 1;
            const float sj0 = s_sqj[c0], sj1 = s_sqj[c1];
            const float2 p0 = __half22float2(*(__half2*)&d[mi][ni][0]);
            const float2 p1 = __half22float2(*(__half2*)&d[mi][ni][1]);
            float e00 = __expf(-(si0 + sj0 - 2.0f * p0.x) * TAU_INV);
            float e01 = __expf(-(si0 + sj1 - 2.0f * p0.y) * TAU_INV);
            float e10 = __expf(-(si1 + sj0 - 2.0f * p1.x) * TAU_INV);
            float e11 = __expf(-(si1 + sj1 - 2.0f * p1.y) * TAU_INV);
            if (diag) {
                if (rl0 == c0) e00 = 0.0f;
                if (rl0 == c1) e01 = 0.0f;
                if (rl1 == c0) e10 = 0.0f;
                if (rl1 == c1) e11 = 0.0f;
            }
            lsum += (e00 + e01) + (e10 + e11);
        }
    }

    #pragma unroll
    for (int o = 16; o > 0; o >>= 1) lsum += __shfl_down_sync(0xffffffffu, lsum, o);
    if (lid == 0) s_red[wid] = lsum;
    __syncthreads();
    if (tid == 0) {
        float bsum = 0.0f;
        #pragma unroll
        for (int i = 0; i < 8; i++) bsum += s_red[i];
        atomicAdd(&g_acc, diag ? (double)bsum : 2.0 * (double)bsum);
    }
}

// ---------------- Kernel 3: finalize ----------------
__global__ void fin_kernel(float* __restrict__ out) {
    out[0] = (float)log(g_acc / ((double)NR * (double)(NR - 1)));
}

extern "C" void kernel_launch(void* const* d_in, const int* in_sizes, int n_in,
                              void* d_out, int out_size) {
    const float* z = (const float*)d_in[0];
    float* out = (float*)d_out;

    prep_kernel<<<NR / 8, 256>>>(z);
    pair_mma_kernel<<<NTILES, 256>>>();
    fin_kernel<<<1, 1>>>(out);
}

// round 11
// speedup vs baseline: 2.4421x; 1.1828x over previous
#include <cuda_runtime.h>
#include <cuda_fp16.h>
#include <stdint.h>
#include <math.h>

#define NR 8192
#define KD 512
#define TM 128
#define KC 32                      // f16 k-chunk: 64 B/row
#define NCH (KD / KC)              // 16 K-chunks
#define NB (NR / TM)               // 64 row blocks
#define NTILES (NB * (NB + 1) / 2) // 2080 upper-triangle tiles
#define ROWB 64                    // SW64-swizzled row stride (no padding)
#define TAU_INV 0.01f

__device__ double g_acc;
__device__ float g_sq[NR];
__device__ __half g_zb[(size_t)NR * KD];   // f16, 8 MB

// SW64 swizzle: conflict-free 8-row x 16B-unit access for 64B rows
#define SW64(off) ((off) ^ (((off) >> 3) & 0x30))

// ---------------- helpers ----------------
__device__ __forceinline__ uint32_t smem_u32(const void* p) {
    uint32_t a;
    asm("{ .reg .u64 t; cvta.to.shared.u64 t, %1; cvt.u32.u64 %0, t; }"
        : "=r"(a) : "l"(p));
    return a;
}
__device__ __forceinline__ void cp_async16(uint32_t s, const void* g) {
    asm volatile("cp.async.cg.shared.global [%0], [%1], 16;" :: "r"(s), "l"(g));
}
#define CP_COMMIT() asm volatile("cp.async.commit_group;" ::: "memory")
#define CP_WAIT1()  asm volatile("cp.async.wait_group 1;" ::: "memory")

__device__ __forceinline__ void ldm_x4(uint32_t* r, uint32_t a) {
    asm volatile("ldmatrix.sync.aligned.m8n8.x4.shared.b16 {%0,%1,%2,%3}, [%4];"
        : "=r"(r[0]), "=r"(r[1]), "=r"(r[2]), "=r"(r[3]) : "r"(a));
}
// f16 x f16 -> f16 accumulate (2 regs = 4 halves)
__device__ __forceinline__ void mma_f16acc(uint32_t* d, const uint32_t* a, const uint32_t* b) {
    asm volatile(
        "mma.sync.aligned.m16n8k16.row.col.f16.f16.f16.f16 "
        "{%0,%1}, {%2,%3,%4,%5}, {%6,%7}, {%0,%1};"
        : "+r"(d[0]), "+r"(d[1])
        : "r"(a[0]), "r"(a[1]), "r"(a[2]), "r"(a[3]), "r"(b[0]), "r"(b[1]));
}

// ---------------- Kernel 1: convert to f16 + fp32 row norms (1 warp/row) ----------------
__global__ void __launch_bounds__(256) prep_kernel(const float* __restrict__ z) {
    const int w = threadIdx.x >> 5, lane = threadIdx.x & 31;
    const int row = blockIdx.x * 8 + w;
    const float4* zr = (const float4*)(z + (size_t)row * KD);
    __half2* dst = (__half2*)(g_zb + (size_t)row * KD);
    float s = 0.0f;
    #pragma unroll
    for (int i = 0; i < 4; i++) {
        const float4 v = zr[lane + 32 * i];
        s += v.x * v.x + v.y * v.y + v.z * v.z + v.w * v.w;
        dst[2 * (lane + 32 * i)]     = __floats2half2_rn(v.x, v.y);
        dst[2 * (lane + 32 * i) + 1] = __floats2half2_rn(v.z, v.w);
    }
    #pragma unroll
    for (int o = 16; o > 0; o >>= 1) s += __shfl_down_sync(0xffffffffu, s, o);
    if (lane == 0) {
        g_sq[row] = s;
        if (row == 0) g_acc = 0.0;
    }
}

// ---------------- Kernel 2: f16-accum HMMA GEMM, 4 warps x 64x64 tiles ----------------
__global__ void __launch_bounds__(128) pair_mma_kernel() {
    __shared__ __align__(16) char sm[2][2][TM * ROWB];   // [stage][A/B]  32 KB
    __shared__ float s_sqi[TM], s_sqj[TM];
    __shared__ float s_red[4];

    const int tid = threadIdx.x;
    const int wid = tid >> 5;         // 0..3
    const int lid = tid & 31;
    const int wr = wid >> 1;          // warp row 0..1  (64 rows each)
    const int wc = wid & 1;           // warp col 0..1  (64 cols each)

    // linear tile index -> (bi, bj) upper triangle
    int t = blockIdx.x, bi = 0;
    while (t >= NB - bi) { t -= NB - bi; bi++; }
    const int bj = bi + t;

    const __half* Ag = g_zb + (size_t)(bi * TM) * KD;
    const __half* Bg = g_zb + (size_t)(bj * TM) * KD;

    uint32_t smA[2], smB[2];
    #pragma unroll
    for (int s = 0; s < 2; s++) {
        smA[s] = smem_u32(sm[s][0]);
        smB[s] = smem_u32(sm[s][1]);
    }

    // chunk = 128 rows x 64 B per matrix = 512 x 16B units; 4 slots/thread/matrix
    auto load_chunk = [&](int kc, int st) {
        #pragma unroll
        for (int i = 0; i < 4; i++) {
            const int f = tid + (i << 7);          // 0..511
            const int r = f >> 2, u = f & 3;
            const uint32_t so = SW64((uint32_t)r * ROWB + (uint32_t)u * 16);
            const size_t go = (size_t)r * KD + (size_t)kc * KC + (size_t)u * 8;
            cp_async16(smA[st] + so, Ag + go);
            cp_async16(smB[st] + so, Bg + go);
        }
    };

    uint32_t d[4][8][2];
    #pragma unroll
    for (int mi = 0; mi < 4; mi++)
        #pragma unroll
        for (int ni = 0; ni < 8; ni++) {
            d[mi][ni][0] = 0u;
            d[mi][ni][1] = 0u;
        }

    load_chunk(0, 0); CP_COMMIT();
    load_chunk(1, 1); CP_COMMIT();

    // fragment lane geometry
    const int a_row = (lid & 15);
    const int a_jofs = (lid >> 4);
    const int b_row = (lid & 7) + ((lid >> 4) << 3);
    const int b_jofs = ((lid >> 3) & 1);

    for (int kc = 0; kc < NCH; kc++) {
        CP_WAIT1();
        __syncthreads();
        const int st = kc & 1;
        #pragma unroll
        for (int kk = 0; kk < 2; kk++) {           // two k=16 steps per chunk
            uint32_t afr[4][4];
            #pragma unroll
            for (int mi = 0; mi < 4; mi++) {
                const int r = wr * 64 + mi * 16 + a_row;
                ldm_x4(afr[mi], smA[st] +
                       SW64((uint32_t)r * ROWB + (uint32_t)(kk * 2 + a_jofs) * 16));
            }
            uint32_t bfr[16];
            #pragma unroll
            for (int nb = 0; nb < 4; nb++) {
                const int n = wc * 64 + nb * 16 + b_row;
                ldm_x4(bfr + nb * 4, smB[st] +
                       SW64((uint32_t)n * ROWB + (uint32_t)(kk * 2 + b_jofs) * 16));
            }
            #pragma unroll
            for (int mi = 0; mi < 4; mi++)
                #pragma unroll
                for (int ni = 0; ni < 8; ni++)
                    mma_f16acc(d[mi][ni], afr[mi], bfr + ni * 2);
        }
        __syncthreads();
        if (kc + 2 < NCH) load_chunk(kc + 2, st);
        CP_COMMIT();
    }

    s_sqi[tid] = g_sq[bi * TM + tid];
    s_sqj[tid] = g_sq[bj * TM + tid];
    __syncthreads();

    // epilogue: D = sqi + sqj - 2*dot -> exp -> sum (skip diagonal)
    const int g = lid >> 2, tt = lid & 3;
    const bool diag = (bi == bj);
    float lsum = 0.0f;
    #pragma unroll
    for (int mi = 0; mi < 4; mi++) {
        const int rl0 = wr * 64 + mi * 16 + g;
        const int rl1 = rl0 + 8;
        const float si0 = s_sqi[rl0], si1 = s_sqi[rl1];
        #pragma unroll
        for (int ni = 0; ni < 8; ni++) {
            const int c0 = wc * 64 + ni * 8 + 2 * tt;
            const int c1 = c0 + 1;
            const float sj0 = s_sqj[c0], sj1 = s_sqj[c1];
            const float2 p0 = __half22float2(*(__half2*)&d[mi][ni][0]);
            const float2 p1 = __half22float2(*(__half2*)&d[mi][ni][1]);
            float e00 = __expf(-(si0 + sj0 - 2.0f * p0.x) * TAU_INV);
            float e01 = __expf(-(si0 + sj1 - 2.0f * p0.y) * TAU_INV);
            float e10 = __expf(-(si1 + sj0 - 2.0f * p1.x) * TAU_INV);
            float e11 = __expf(-(si1 + sj1 - 2.0f * p1.y) * TAU_INV);
            if (diag) {
                if (rl0 == c0) e00 = 0.0f;
                if (rl0 == c1) e01 = 0.0f;
                if (rl1 == c0) e10 = 0.0f;
                if (rl1 == c1) e11 = 0.0f;
            }
            lsum += (e00 + e01) + (e10 + e11);
        }
    }

    #pragma unroll
    for (int o = 16; o > 0; o >>= 1) lsum += __shfl_down_sync(0xffffffffu, lsum, o);
    if (lid == 0) s_red[wid] = lsum;
    __syncthreads();
    if (tid == 0) {
        const float bsum = (s_red[0] + s_red[1]) + (s_red[2] + s_red[3]);
        atomicAdd(&g_acc, diag ? (double)bsum : 2.0 * (double)bsum);
    }
}

// ---------------- Kernel 3: finalize ----------------
__global__ void fin_kernel(float* __restrict__ out) {
    out[0] = (float)log(g_acc / ((double)NR * (double)(NR - 1)));
}

extern "C" void kernel_launch(void* const* d_in, const int* in_sizes, int n_in,
                              void* d_out, int out_size) {
    const float* z = (const float*)d_in[0];
    float* out = (float*)d_out;

    prep_kernel<<<NR / 8, 256>>>(z);
    pair_mma_kernel<<<NTILES, 128>>>();
    fin_kernel<<<1, 1>>>(out);
}